// round 2
// baseline (speedup 1.0000x reference)
#include <cuda_runtime.h>

// Fused SegmentationAugmentation:
//   out[0 .. 2^24)     = trilinear(border) affine sample of input_g   (float)
//   out[2^24 .. 2^25)  = (same sample of label_g) > 0.5               (1.0f/0.0f)
//
// All floating-point ops on the sampling path use __fmul_rn/__fadd_rn/__fsub_rn
// to forbid FMA contraction and replicate the reference (XLA, no-contract,
// left-associated) rounding sequence bit-exactly. This matters only for the
// boolean threshold on output 1, but both outputs share the math.

#define N_VOX (1 << 24)   // 8 * 128^3

__global__ __launch_bounds__(256)
void seg_aug_kernel(const float* __restrict__ inp,
                    const float* __restrict__ lab,
                    const float* __restrict__ T,
                    float* __restrict__ out)
{
    const int idx = blockIdx.x * blockDim.x + threadIdx.x;

    const int w = idx & 127;          // contiguous axis (orig W)
    const int h = (idx >> 7) & 127;   // orig H
    const int d = (idx >> 14) & 127;  // orig D
    const int b = idx >> 21;

    // pixel-center normalized coords: (2i+1)/128 - 1  (exact in fp32)
    const float inv128 = 1.0f / 128.0f;
    const float xn = (2.0f * (float)d + 1.0f) * inv128 - 1.0f;
    const float yn = (2.0f * (float)h + 1.0f) * inv128 - 1.0f;
    const float zn = (2.0f * (float)w + 1.0f) * inv128 - 1.0f;

    const float t00 = __ldg(T + 0), t01 = __ldg(T + 1), t02 = __ldg(T + 2),  t03 = __ldg(T + 3);
    const float t10 = __ldg(T + 4), t11 = __ldg(T + 5), t12 = __ldg(T + 6),  t13 = __ldg(T + 7);
    const float t20 = __ldg(T + 8), t21 = __ldg(T + 9), t22 = __ldg(T + 10), t23 = __ldg(T + 11);

    // einsum reduce order: ((t0*x + t1*y) + t2*z), then separate + translation
    const float xs = __fadd_rn(__fadd_rn(__fadd_rn(__fmul_rn(t00, xn), __fmul_rn(t01, yn)),
                                         __fmul_rn(t02, zn)), t03);
    const float ys = __fadd_rn(__fadd_rn(__fadd_rn(__fmul_rn(t10, xn), __fmul_rn(t11, yn)),
                                         __fmul_rn(t12, zn)), t13);
    const float zs = __fadd_rn(__fadd_rn(__fadd_rn(__fmul_rn(t20, xn), __fmul_rn(t21, yn)),
                                         __fmul_rn(t22, zn)), t23);

    // unnorm: clip(((c+1)*128 - 1)*0.5, 0, 127)  — no contraction
    const float X = fminf(fmaxf(__fmul_rn(__fsub_rn(__fmul_rn(__fadd_rn(xs, 1.0f), 128.0f), 1.0f), 0.5f), 0.0f), 127.0f);
    const float Y = fminf(fmaxf(__fmul_rn(__fsub_rn(__fmul_rn(__fadd_rn(ys, 1.0f), 128.0f), 1.0f), 0.5f), 0.0f), 127.0f);
    const float Z = fminf(fmaxf(__fmul_rn(__fsub_rn(__fmul_rn(__fadd_rn(zs, 1.0f), 128.0f), 1.0f), 0.5f), 0.0f), 127.0f);

    const float x0f = floorf(X), y0f = floorf(Y), z0f = floorf(Z);
    const float fx = __fsub_rn(X, x0f);
    const float fy = __fsub_rn(Y, y0f);
    const float fz = __fsub_rn(Z, z0f);
    const int x0 = (int)x0f, y0 = (int)y0f, z0 = (int)z0f;
    const int x1 = min(x0 + 1, 127);
    const int y1 = min(y0 + 1, 127);
    const int z1 = min(z0 + 1, 127);

    const float wx0 = __fsub_rn(1.0f, fx), wx1 = fx;
    const float wy0 = __fsub_rn(1.0f, fy), wy1 = fy;
    const float wz0 = __fsub_rn(1.0f, fz), wz1 = fz;

    // per-corner weight = (wz * wy) * wx  (left-assoc, as in reference)
    const float w00_ = __fmul_rn(wz0, wy0);
    const float w01_ = __fmul_rn(wz0, wy1);
    const float w10_ = __fmul_rn(wz1, wy0);
    const float w11_ = __fmul_rn(wz1, wy1);

    const float wA = __fmul_rn(w00_, wx0);  // (z0,y0,x0)
    const float wB = __fmul_rn(w00_, wx1);  // (z0,y0,x1)
    const float wC = __fmul_rn(w01_, wx0);  // (z0,y1,x0)
    const float wD = __fmul_rn(w01_, wx1);  // (z0,y1,x1)
    const float wE = __fmul_rn(w10_, wx0);  // (z1,y0,x0)
    const float wF = __fmul_rn(w10_, wx1);  // (z1,y0,x1)
    const float wG = __fmul_rn(w11_, wx0);  // (z1,y1,x0)
    const float wH = __fmul_rn(w11_, wx1);  // (z1,y1,x1)

    // memory index in original layout: ((b*128 + x)*128 + y)*128 + z
    const int base = b << 21;
    const int r00 = base + (x0 << 14) + (y0 << 7);  // x0,y0
    const int r01 = base + (x0 << 14) + (y1 << 7);  // x0,y1
    const int r10 = base + (x1 << 14) + (y0 << 7);  // x1,y0
    const int r11 = base + (x1 << 14) + (y1 << 7);  // x1,y1

    // reference accumulation order: z outer, y mid, x inner
    {
        float acc = 0.0f;
        acc = __fadd_rn(acc, __fmul_rn(__ldg(inp + r00 + z0), wA));
        acc = __fadd_rn(acc, __fmul_rn(__ldg(inp + r10 + z0), wB));
        acc = __fadd_rn(acc, __fmul_rn(__ldg(inp + r01 + z0), wC));
        acc = __fadd_rn(acc, __fmul_rn(__ldg(inp + r11 + z0), wD));
        acc = __fadd_rn(acc, __fmul_rn(__ldg(inp + r00 + z1), wE));
        acc = __fadd_rn(acc, __fmul_rn(__ldg(inp + r10 + z1), wF));
        acc = __fadd_rn(acc, __fmul_rn(__ldg(inp + r01 + z1), wG));
        acc = __fadd_rn(acc, __fmul_rn(__ldg(inp + r11 + z1), wH));
        out[idx] = acc;
    }
    {
        float acc = 0.0f;
        acc = __fadd_rn(acc, __fmul_rn(__ldg(lab + r00 + z0), wA));
        acc = __fadd_rn(acc, __fmul_rn(__ldg(lab + r10 + z0), wB));
        acc = __fadd_rn(acc, __fmul_rn(__ldg(lab + r01 + z0), wC));
        acc = __fadd_rn(acc, __fmul_rn(__ldg(lab + r11 + z0), wD));
        acc = __fadd_rn(acc, __fmul_rn(__ldg(lab + r00 + z1), wE));
        acc = __fadd_rn(acc, __fmul_rn(__ldg(lab + r10 + z1), wF));
        acc = __fadd_rn(acc, __fmul_rn(__ldg(lab + r01 + z1), wG));
        acc = __fadd_rn(acc, __fmul_rn(__ldg(lab + r11 + z1), wH));
        out[idx + N_VOX] = (acc > 0.5f) ? 1.0f : 0.0f;
    }
}

extern "C" void kernel_launch(void* const* d_in, const int* in_sizes, int n_in,
                              void* d_out, int out_size)
{
    const float* inp = (const float*)d_in[0];   // input_g  [8,1,128,128,128]
    const float* lab = (const float*)d_in[1];   // label_g  [8,1,128,128,128]
    const float* T   = (const float*)d_in[2];   // transform 4x4 (16 floats)
    float* out = (float*)d_out;

    const int threads = 256;
    const int blocks = N_VOX / threads;         // 65536
    seg_aug_kernel<<<blocks, threads>>>(inp, lab, T, out);
}

// round 3
// speedup vs baseline: 1.1744x; 1.1744x over previous
#include <cuda_runtime.h>

// Fused SegmentationAugmentation, row-hoisted:
//   out[0 .. 2^24)     = trilinear(border) affine sample of input_g   (float)
//   out[2^24 .. 2^25)  = (same sample of label_g) > 0.5               (1.0f/0.0f)
//
// One warp per output (b,d,h) row of 128 voxels; lane handles w = lane + 32k.
// Since T = t @ rot(z) has T[0,2] = T[1,2] = 0, the x/y sampling pipeline
// (coords, floors, fractional weights, 4 input-row bases) is constant along
// the row and hoisted (warp-uniform fast path, with exact generic fallback).
// All FP ops use __f*_rn to replicate the reference rounding bit-exactly.

#define N_VOX (1 << 24)   // 8 * 128^3

__device__ __forceinline__ float unnorm_clamp(float c)
{
    // clip(((c+1)*128 - 1)*0.5, 0, 127) with reference rounding sequence
    return fminf(fmaxf(__fmul_rn(__fsub_rn(__fmul_rn(__fadd_rn(c, 1.0f), 128.0f), 1.0f), 0.5f),
                       0.0f), 127.0f);
}

__global__ __launch_bounds__(256)
void seg_aug_kernel(const float* __restrict__ inp,
                    const float* __restrict__ lab,
                    const float* __restrict__ T,
                    float* __restrict__ out)
{
    const int lane = threadIdx.x & 31;
    const int row  = blockIdx.x * 8 + (threadIdx.x >> 5);  // 131072 rows total

    const int h = row & 127;
    const int d = (row >> 7) & 127;
    const int b = row >> 14;

    const float inv128 = 1.0f / 128.0f;
    const float xn = (2.0f * (float)d + 1.0f) * inv128 - 1.0f;
    const float yn = (2.0f * (float)h + 1.0f) * inv128 - 1.0f;

    const float t00 = __ldg(T + 0), t01 = __ldg(T + 1), t02 = __ldg(T + 2),  t03 = __ldg(T + 3);
    const float t10 = __ldg(T + 4), t11 = __ldg(T + 5), t12 = __ldg(T + 6),  t13 = __ldg(T + 7);
    const float t20 = __ldg(T + 8), t21 = __ldg(T + 9), t22 = __ldg(T + 10), t23 = __ldg(T + 11);

    // exact reference prefixes (t0*xn + t1*yn), constant along the row
    const float ux = __fadd_rn(__fmul_rn(t00, xn), __fmul_rn(t01, yn));
    const float uy = __fadd_rn(__fmul_rn(t10, xn), __fmul_rn(t11, yn));
    const float uz = __fadd_rn(__fmul_rn(t20, xn), __fmul_rn(t21, yn));

    const int out_base = row << 7;
    const int vol_base = b << 21;

    const bool fastxy = (t02 == 0.0f) && (t12 == 0.0f);   // warp-uniform

    if (fastxy) {
        // x/y pipeline hoisted out of the w loop (bit-exact: +/-0 * zn
        // addition cannot change the clamped coordinate)
        const float xs = __fadd_rn(ux, t03);
        const float ys = __fadd_rn(uy, t13);
        const float X = unnorm_clamp(xs);
        const float Y = unnorm_clamp(ys);
        const float x0f = floorf(X), y0f = floorf(Y);
        const float fx = __fsub_rn(X, x0f);
        const float fy = __fsub_rn(Y, y0f);
        const int x0 = (int)x0f, y0 = (int)y0f;
        const int x1 = min(x0 + 1, 127);
        const int y1 = min(y0 + 1, 127);
        const float wx0 = __fsub_rn(1.0f, fx), wx1 = fx;
        const float wy0 = __fsub_rn(1.0f, fy), wy1 = fy;

        const float* pi00 = inp + vol_base + (x0 << 14) + (y0 << 7);
        const float* pi01 = inp + vol_base + (x0 << 14) + (y1 << 7);
        const float* pi10 = inp + vol_base + (x1 << 14) + (y0 << 7);
        const float* pi11 = inp + vol_base + (x1 << 14) + (y1 << 7);
        const float* pl00 = lab + vol_base + (x0 << 14) + (y0 << 7);
        const float* pl01 = lab + vol_base + (x0 << 14) + (y1 << 7);
        const float* pl10 = lab + vol_base + (x1 << 14) + (y0 << 7);
        const float* pl11 = lab + vol_base + (x1 << 14) + (y1 << 7);

        #pragma unroll
        for (int k = 0; k < 4; k++) {
            const int w = lane + 32 * k;
            const float zn = (2.0f * (float)w + 1.0f) * inv128 - 1.0f;
            const float zs = __fadd_rn(__fadd_rn(uz, __fmul_rn(t22, zn)), t23);
            const float Z = unnorm_clamp(zs);
            const float z0f = floorf(Z);
            const float fz = __fsub_rn(Z, z0f);
            const int z0 = (int)z0f;
            const int z1 = min(z0 + 1, 127);
            const float wz0 = __fsub_rn(1.0f, fz), wz1 = fz;

            const float m00 = __fmul_rn(wz0, wy0);
            const float m01 = __fmul_rn(wz0, wy1);
            const float m10 = __fmul_rn(wz1, wy0);
            const float m11 = __fmul_rn(wz1, wy1);
            const float wA = __fmul_rn(m00, wx0), wB = __fmul_rn(m00, wx1);
            const float wC = __fmul_rn(m01, wx0), wD = __fmul_rn(m01, wx1);
            const float wE = __fmul_rn(m10, wx0), wF = __fmul_rn(m10, wx1);
            const float wG = __fmul_rn(m11, wx0), wH = __fmul_rn(m11, wx1);

            float acc = 0.0f;
            acc = __fadd_rn(acc, __fmul_rn(__ldg(pi00 + z0), wA));
            acc = __fadd_rn(acc, __fmul_rn(__ldg(pi10 + z0), wB));
            acc = __fadd_rn(acc, __fmul_rn(__ldg(pi01 + z0), wC));
            acc = __fadd_rn(acc, __fmul_rn(__ldg(pi11 + z0), wD));
            acc = __fadd_rn(acc, __fmul_rn(__ldg(pi00 + z1), wE));
            acc = __fadd_rn(acc, __fmul_rn(__ldg(pi10 + z1), wF));
            acc = __fadd_rn(acc, __fmul_rn(__ldg(pi01 + z1), wG));
            acc = __fadd_rn(acc, __fmul_rn(__ldg(pi11 + z1), wH));
            out[out_base + w] = acc;

            float accl = 0.0f;
            accl = __fadd_rn(accl, __fmul_rn(__ldg(pl00 + z0), wA));
            accl = __fadd_rn(accl, __fmul_rn(__ldg(pl10 + z0), wB));
            accl = __fadd_rn(accl, __fmul_rn(__ldg(pl01 + z0), wC));
            accl = __fadd_rn(accl, __fmul_rn(__ldg(pl11 + z0), wD));
            accl = __fadd_rn(accl, __fmul_rn(__ldg(pl00 + z1), wE));
            accl = __fadd_rn(accl, __fmul_rn(__ldg(pl10 + z1), wF));
            accl = __fadd_rn(accl, __fmul_rn(__ldg(pl01 + z1), wG));
            accl = __fadd_rn(accl, __fmul_rn(__ldg(pl11 + z1), wH));
            out[out_base + w + N_VOX] = (accl > 0.5f) ? 1.0f : 0.0f;
        }
    } else {
        // generic exact path: per-voxel full coordinate pipeline
        #pragma unroll
        for (int k = 0; k < 4; k++) {
            const int w = lane + 32 * k;
            const float zn = (2.0f * (float)w + 1.0f) * inv128 - 1.0f;
            const float xs = __fadd_rn(__fadd_rn(ux, __fmul_rn(t02, zn)), t03);
            const float ys = __fadd_rn(__fadd_rn(uy, __fmul_rn(t12, zn)), t13);
            const float zs = __fadd_rn(__fadd_rn(uz, __fmul_rn(t22, zn)), t23);
            const float X = unnorm_clamp(xs);
            const float Y = unnorm_clamp(ys);
            const float Z = unnorm_clamp(zs);
            const float x0f = floorf(X), y0f = floorf(Y), z0f = floorf(Z);
            const float fx = __fsub_rn(X, x0f);
            const float fy = __fsub_rn(Y, y0f);
            const float fz = __fsub_rn(Z, z0f);
            const int x0 = (int)x0f, y0 = (int)y0f, z0 = (int)z0f;
            const int x1 = min(x0 + 1, 127);
            const int y1 = min(y0 + 1, 127);
            const int z1 = min(z0 + 1, 127);
            const float wx0 = __fsub_rn(1.0f, fx), wx1 = fx;
            const float wy0 = __fsub_rn(1.0f, fy), wy1 = fy;
            const float wz0 = __fsub_rn(1.0f, fz), wz1 = fz;

            const int r00 = vol_base + (x0 << 14) + (y0 << 7);
            const int r01 = vol_base + (x0 << 14) + (y1 << 7);
            const int r10 = vol_base + (x1 << 14) + (y0 << 7);
            const int r11 = vol_base + (x1 << 14) + (y1 << 7);

            const float m00 = __fmul_rn(wz0, wy0);
            const float m01 = __fmul_rn(wz0, wy1);
            const float m10 = __fmul_rn(wz1, wy0);
            const float m11 = __fmul_rn(wz1, wy1);
            const float wA = __fmul_rn(m00, wx0), wB = __fmul_rn(m00, wx1);
            const float wC = __fmul_rn(m01, wx0), wD = __fmul_rn(m01, wx1);
            const float wE = __fmul_rn(m10, wx0), wF = __fmul_rn(m10, wx1);
            const float wG = __fmul_rn(m11, wx0), wH = __fmul_rn(m11, wx1);

            float acc = 0.0f;
            acc = __fadd_rn(acc, __fmul_rn(__ldg(inp + r00 + z0), wA));
            acc = __fadd_rn(acc, __fmul_rn(__ldg(inp + r10 + z0), wB));
            acc = __fadd_rn(acc, __fmul_rn(__ldg(inp + r01 + z0), wC));
            acc = __fadd_rn(acc, __fmul_rn(__ldg(inp + r11 + z0), wD));
            acc = __fadd_rn(acc, __fmul_rn(__ldg(inp + r00 + z1), wE));
            acc = __fadd_rn(acc, __fmul_rn(__ldg(inp + r10 + z1), wF));
            acc = __fadd_rn(acc, __fmul_rn(__ldg(inp + r01 + z1), wG));
            acc = __fadd_rn(acc, __fmul_rn(__ldg(inp + r11 + z1), wH));
            out[out_base + w] = acc;

            float accl = 0.0f;
            accl = __fadd_rn(accl, __fmul_rn(__ldg(lab + r00 + z0), wA));
            accl = __fadd_rn(accl, __fmul_rn(__ldg(lab + r10 + z0), wB));
            accl = __fadd_rn(accl, __fmul_rn(__ldg(lab + r01 + z0), wC));
            accl = __fadd_rn(accl, __fmul_rn(__ldg(lab + r11 + z0), wD));
            accl = __fadd_rn(accl, __fmul_rn(__ldg(lab + r00 + z1), wE));
            accl = __fadd_rn(accl, __fmul_rn(__ldg(lab + r10 + z1), wF));
            accl = __fadd_rn(accl, __fmul_rn(__ldg(lab + r01 + z1), wG));
            accl = __fadd_rn(accl, __fmul_rn(__ldg(lab + r11 + z1), wH));
            out[out_base + w + N_VOX] = (accl > 0.5f) ? 1.0f : 0.0f;
        }
    }
}

extern "C" void kernel_launch(void* const* d_in, const int* in_sizes, int n_in,
                              void* d_out, int out_size)
{
    const float* inp = (const float*)d_in[0];   // input_g  [8,1,128,128,128]
    const float* lab = (const float*)d_in[1];   // label_g  [8,1,128,128,128]
    const float* T   = (const float*)d_in[2];   // transform 4x4 (16 floats)
    float* out = (float*)d_out;

    // 131072 rows, 8 rows (warps) per block
    seg_aug_kernel<<<16384, 256>>>(inp, lab, T, out);
}